// round 5
// baseline (speedup 1.0000x reference)
#include <cuda_runtime.h>
#include <stdint.h>

#define D 128
#define DV 32              // float4 chunks per row
#define MAXN 50048
#define MAXE 1600000

// Zero-initialized at module load. Invariant: g_deg and g_cnt are all-zero at
// entry to kernel_launch, and every call restores that before it returns
// (k_scan_dis zeroes deg; the last k_gemm zeroes cnt).
__device__ int    g_deg[MAXN];
__device__ int    g_cnt[MAXN];        // in-counts, then scatter cursors, then counts
__device__ int2   g_adj[MAXE];        // dst-sorted: {src, __float_as_int(dis[src])}
__device__ int    g_start[MAXN + 1];  // CSR offsets by dst
__device__ float  g_dis[MAXN];
__device__ float  g_a[MAXN * D];      // aggregated features
__device__ float  g_h[MAXN * D];      // hidden after layer 1

// ---------------------------------------------------------------------------
// Per-block dtype detect: int64 little-endian values < 2^32 -> odd 32-bit
// words all zero. Checks 128 odd words; int32 node ids in [0,50000) make a
// false positive essentially impossible. Costs 2 cached loads per lane.
// Returns via shared flag; call with full block, includes __syncthreads.
// ---------------------------------------------------------------------------
__device__ __forceinline__ int detect_is64(const unsigned* p, int* s_flag) {
    if (threadIdx.x == 0) *s_flag = 0;
    __syncthreads();
    if (threadIdx.x < 64) {
        unsigned nz = p[2 * threadIdx.x + 1] | p[2 * threadIdx.x + 129];
        if (nz) atomicOr(s_flag, 1);
    }
    __syncthreads();
    return *s_flag ? 0 : 1;
}

// Parse edges (either dtype) and count: deg by row (+1 self handled later),
// cnt by col.
__global__ void k_prep(const void* p, int E) {
    __shared__ int s_flag;
    int is64 = detect_is64((const unsigned*)p, &s_flag);
    int e = blockIdx.x * blockDim.x + threadIdx.x;
    if (e >= E) return;
    int r, c;
    if (is64) {
        const long long* q = (const long long*)p;
        r = (int)q[e];
        c = (int)q[(long long)E + e];
    } else {
        const int* q = (const int*)p;
        r = q[e];
        c = q[E + e];
    }
    atomicAdd(&g_deg[r], 1);
    atomicAdd(&g_cnt[c], 1);
}

// Single block: exclusive scan of g_cnt -> g_start, zero cursors,
// dis = rsqrt(deg+1)  (the +1 is the self loop), and re-zero g_deg to
// restore the entry invariant.
__global__ void k_scan_dis(int N, int E) {
    __shared__ int sh[1024];
    const int tid = threadIdx.x;
    const int per = (N + 1023) >> 10;
    const int base = tid * per;
    int s = 0;
    for (int i = 0; i < per; i++) {
        int idx = base + i;
        if (idx < N) s += g_cnt[idx];
    }
    sh[tid] = s;
    __syncthreads();
    for (int off = 1; off < 1024; off <<= 1) {
        int t = (tid >= off) ? sh[tid - off] : 0;
        __syncthreads();
        sh[tid] += t;
        __syncthreads();
    }
    int run = sh[tid] - s;   // exclusive prefix for this thread's range
    for (int i = 0; i < per; i++) {
        int idx = base + i;
        if (idx < N) {
            int c = g_cnt[idx];
            g_start[idx] = run;
            run += c;
            g_cnt[idx] = 0;
            g_dis[idx] = rsqrtf((float)(g_deg[idx] + 1));
            g_deg[idx] = 0;   // restore invariant
        }
    }
    if (tid == 0) g_start[N] = E;
}

// Scatter edges into dst-sorted adjacency with per-edge weight dis[src].
// Re-parses the raw edge input (no row/col staging arrays).
__global__ void k_scatter(const void* p, int E) {
    __shared__ int s_flag;
    int is64 = detect_is64((const unsigned*)p, &s_flag);
    int e = blockIdx.x * blockDim.x + threadIdx.x;
    if (e >= E) return;
    int r, c;
    if (is64) {
        const long long* q = (const long long*)p;
        r = (int)q[e];
        c = (int)q[(long long)E + e];
    } else {
        const int* q = (const int*)p;
        r = q[e];
        c = q[E + e];
    }
    int pos = g_start[c] + atomicAdd(&g_cnt[c], 1);
    g_adj[pos] = make_int2(r, __float_as_int(g_dis[r]));
}

// ---------------------------------------------------------------------------
// Aggregation: one warp per dst node, fp32 float4 gather, 4 edges in flight,
// 4 independent accumulators.
// dst = dis[n]*(sum_e dis[src]*x[src]) + dis[n]^2 * x[n]
// ---------------------------------------------------------------------------
__global__ void k_agg(const float4* __restrict__ src, float4* __restrict__ dst, int N) {
    int w = (blockIdx.x * blockDim.x + threadIdx.x) >> 5;
    if (w >= N) return;
    const int lane = threadIdx.x & 31;
    int i = g_start[w];
    const int end = g_start[w + 1];

    float4 a0 = make_float4(0.f, 0.f, 0.f, 0.f);
    float4 a1 = make_float4(0.f, 0.f, 0.f, 0.f);
    float4 a2 = make_float4(0.f, 0.f, 0.f, 0.f);
    float4 a3 = make_float4(0.f, 0.f, 0.f, 0.f);

    for (; i + 4 <= end; i += 4) {
        int2 e0 = __ldg(&g_adj[i]);
        int2 e1 = __ldg(&g_adj[i + 1]);
        int2 e2 = __ldg(&g_adj[i + 2]);
        int2 e3 = __ldg(&g_adj[i + 3]);
        float4 v0 = __ldg(&src[(long)e0.x * DV + lane]);
        float4 v1 = __ldg(&src[(long)e1.x * DV + lane]);
        float4 v2 = __ldg(&src[(long)e2.x * DV + lane]);
        float4 v3 = __ldg(&src[(long)e3.x * DV + lane]);
        float w0 = __int_as_float(e0.y);
        float w1 = __int_as_float(e1.y);
        float w2 = __int_as_float(e2.y);
        float w3 = __int_as_float(e3.y);
        a0.x += w0 * v0.x; a0.y += w0 * v0.y; a0.z += w0 * v0.z; a0.w += w0 * v0.w;
        a1.x += w1 * v1.x; a1.y += w1 * v1.y; a1.z += w1 * v1.z; a1.w += w1 * v1.w;
        a2.x += w2 * v2.x; a2.y += w2 * v2.y; a2.z += w2 * v2.z; a2.w += w2 * v2.w;
        a3.x += w3 * v3.x; a3.y += w3 * v3.y; a3.z += w3 * v3.z; a3.w += w3 * v3.w;
    }
    for (; i < end; i++) {
        int2 e0 = __ldg(&g_adj[i]);
        float4 v0 = __ldg(&src[(long)e0.x * DV + lane]);
        float w0 = __int_as_float(e0.y);
        a0.x += w0 * v0.x; a0.y += w0 * v0.y; a0.z += w0 * v0.z; a0.w += w0 * v0.w;
    }

    float di = g_dis[w];
    float sw = di * di;
    float4 sv = __ldg(&src[(long)w * DV + lane]);
    float4 o;
    o.x = di * ((a0.x + a1.x) + (a2.x + a3.x)) + sw * sv.x;
    o.y = di * ((a0.y + a1.y) + (a2.y + a3.y)) + sw * sv.y;
    o.z = di * ((a0.z + a1.z) + (a2.z + a3.z)) + sw * sv.z;
    o.w = di * ((a0.w + a1.w) + (a2.w + a3.w)) + sw * sv.w;
    dst[(long)w * DV + lane] = o;
}

// ---------------------------------------------------------------------------
// GEMM: C[N,128] = A[N,128] @ W[128,128] + bias, optional ReLU.
// BM=128, BN=128, BK=32, 256 threads, 8x8 register tile, register
// double-buffer on the k-tiles. CLEAN re-zeroes g_cnt (invariant restore).
// ---------------------------------------------------------------------------
template <bool RELU, bool CLEAN>
__global__ void __launch_bounds__(256)
k_gemm(const float* __restrict__ A, const float* __restrict__ W,
       const float* __restrict__ bias, float* __restrict__ C, int N) {
    __shared__ float As[32][129];   // [k][m]
    __shared__ float Ws[32][128];   // [k][n]

    const int tid = threadIdx.x;
    if (CLEAN) {
        int idx = blockIdx.x * blockDim.x + tid;
        if (idx < MAXN) g_cnt[idx] = 0;
    }
    const int tm = tid >> 4;    // 0..15 -> 8 rows each
    const int tn = tid & 15;    // 0..15 -> 8 cols each
    const int row0 = blockIdx.x * 128;

    // Per-thread load slots: A 4x float4, W 4x float4
    const int am  = tid >> 3;          // A row in tile for slot 0 (stride 32 rows)
    const int ak4 = tid & 7;           // A float4-k index
    const int wk  = tid >> 5;          // W k for slot 0 (stride 8)
    const int wn4 = tid & 31;          // W float4-n index

    float4 pa[4], pw[4];
    auto load_tiles = [&](int kk) {
        #pragma unroll
        for (int it = 0; it < 4; it++) {
            int gr = row0 + am + it * 32;
            pa[it] = (gr < N) ? *(const float4*)(A + (long)gr * D + kk + ak4 * 4)
                              : make_float4(0.f, 0.f, 0.f, 0.f);
        }
        #pragma unroll
        for (int it = 0; it < 4; it++)
            pw[it] = *(const float4*)(W + (kk + wk + it * 8) * D + wn4 * 4);
    };
    auto store_tiles = [&]() {
        #pragma unroll
        for (int it = 0; it < 4; it++) {
            int m = am + it * 32;
            As[ak4 * 4 + 0][m] = pa[it].x;
            As[ak4 * 4 + 1][m] = pa[it].y;
            As[ak4 * 4 + 2][m] = pa[it].z;
            As[ak4 * 4 + 3][m] = pa[it].w;
        }
        #pragma unroll
        for (int it = 0; it < 4; it++)
            *(float4*)&Ws[wk + it * 8][wn4 * 4] = pw[it];
    };

    float acc[8][8];
    #pragma unroll
    for (int i = 0; i < 8; i++)
        #pragma unroll
        for (int j = 0; j < 8; j++) acc[i][j] = 0.f;

    load_tiles(0);
    for (int kk = 0; kk < D; kk += 32) {
        store_tiles();
        __syncthreads();
        if (kk + 32 < D) load_tiles(kk + 32);

        #pragma unroll 8
        for (int k = 0; k < 32; k++) {
            float a[8], b[8];
            #pragma unroll
            for (int j = 0; j < 8; j++) a[j] = As[k][tm * 8 + j];
            float4 b0 = *(const float4*)&Ws[k][tn * 8];
            float4 b1 = *(const float4*)&Ws[k][tn * 8 + 4];
            b[0] = b0.x; b[1] = b0.y; b[2] = b0.z; b[3] = b0.w;
            b[4] = b1.x; b[5] = b1.y; b[6] = b1.z; b[7] = b1.w;
            #pragma unroll
            for (int i = 0; i < 8; i++)
                #pragma unroll
                for (int j = 0; j < 8; j++)
                    acc[i][j] += a[i] * b[j];
        }
        __syncthreads();
    }

    float4 bv0 = *(const float4*)(bias + tn * 8);
    float4 bv1 = *(const float4*)(bias + tn * 8 + 4);
    #pragma unroll
    for (int i = 0; i < 8; i++) {
        int gr = row0 + tm * 8 + i;
        if (gr >= N) continue;
        float o[8];
        o[0] = acc[i][0] + bv0.x; o[1] = acc[i][1] + bv0.y;
        o[2] = acc[i][2] + bv0.z; o[3] = acc[i][3] + bv0.w;
        o[4] = acc[i][4] + bv1.x; o[5] = acc[i][5] + bv1.y;
        o[6] = acc[i][6] + bv1.z; o[7] = acc[i][7] + bv1.w;
        if (RELU) {
            #pragma unroll
            for (int j = 0; j < 8; j++) o[j] = fmaxf(o[j], 0.f);
        }
        *(float4*)(C + (long)gr * D + tn * 8)     = make_float4(o[0], o[1], o[2], o[3]);
        *(float4*)(C + (long)gr * D + tn * 8 + 4) = make_float4(o[4], o[5], o[6], o[7]);
    }
}

extern "C" void kernel_launch(void* const* d_in, const int* in_sizes, int n_in,
                              void* d_out, int out_size) {
    const float* x  = (const float*)d_in[0];
    const void*  ei = d_in[1];
    const float* W1 = (const float*)d_in[2];
    const float* b1 = (const float*)d_in[3];
    const float* W2 = (const float*)d_in[4];
    const float* b2 = (const float*)d_in[5];
    float* out = (float*)d_out;

    const int N = in_sizes[0] / D;
    const int E = in_sizes[1] / 2;

    float* a_ptr = nullptr;
    float* h_ptr = nullptr;
    cudaGetSymbolAddress((void**)&a_ptr, g_a);
    cudaGetSymbolAddress((void**)&h_ptr, g_h);

    const int T = 256;
    const int eGrid = (E + T - 1) / T;
    const int aggGrid  = (N * 32 + T - 1) / T;
    const int gemmGrid = (N + 127) / 128;

    // ---- prep (3 launches; deg/cnt arrive zeroed by invariant) ----
    k_prep<<<eGrid, T>>>(ei, E);
    k_scan_dis<<<1, 1024>>>(N, E);
    k_scatter<<<eGrid, T>>>(ei, E);

    // ---- layer 1 (k_agg is launch #4 -> lands in the ncu sample slot) ----
    k_agg<<<aggGrid, T>>>((const float4*)x, (float4*)a_ptr, N);
    k_gemm<true, false><<<gemmGrid, T>>>(a_ptr, W1, b1, h_ptr, N);

    // ---- layer 2 (final gemm restores g_cnt = 0) ----
    k_agg<<<aggGrid, T>>>((const float4*)h_ptr, (float4*)a_ptr, N);
    k_gemm<false, true><<<gemmGrid, T>>>(a_ptr, W2, b2, out, N);
}

// round 6
// speedup vs baseline: 1.0513x; 1.0513x over previous
#include <cuda_runtime.h>
#include <stdint.h>

#define D 128
#define DV 32              // float4 chunks per row
#define MAXN 50048
#define MAXE 1600000

// Zero-initialized at module load. Invariant: g_deg and g_cnt are all-zero at
// entry to kernel_launch, and every call restores that before it returns
// (k_scan_dis zeroes deg; the last k_gemm zeroes cnt).
__device__ int    g_deg[MAXN];
__device__ int    g_cnt[MAXN];        // in-counts, then scatter cursors, then counts
__device__ int2   g_adj[MAXE];        // dst-sorted: {src, __float_as_int(dis[src])}
__device__ int    g_start[MAXN + 1];  // CSR offsets by dst
__device__ float  g_dis[MAXN];
__device__ float  g_a[MAXN * D];      // aggregated features
__device__ float  g_h[MAXN * D];      // hidden after layer 1

// ---------------------------------------------------------------------------
// Per-block dtype detect: int64 little-endian values < 2^32 -> odd 32-bit
// words all zero. Checks 128 odd words; false positive essentially impossible
// for int32 node ids. Two cached loads per participating lane.
// ---------------------------------------------------------------------------
__device__ __forceinline__ int detect_is64(const unsigned* p, int* s_flag) {
    if (threadIdx.x == 0) *s_flag = 0;
    __syncthreads();
    if (threadIdx.x < 64) {
        unsigned nz = p[2 * threadIdx.x + 1] | p[2 * threadIdx.x + 129];
        if (nz) atomicOr(s_flag, 1);
    }
    __syncthreads();
    return *s_flag ? 0 : 1;
}

// Parse edges (either dtype) and count degrees.
__global__ void k_prep(const void* p, int E) {
    __shared__ int s_flag;
    int is64 = detect_is64((const unsigned*)p, &s_flag);
    int e = blockIdx.x * blockDim.x + threadIdx.x;
    if (e >= E) return;
    int r, c;
    if (is64) {
        const long long* q = (const long long*)p;
        r = (int)q[e];
        c = (int)q[(long long)E + e];
    } else {
        const int* q = (const int*)p;
        r = q[e];
        c = q[E + e];
    }
    atomicAdd(&g_deg[r], 1);
    atomicAdd(&g_cnt[c], 1);
}

// Single block: exclusive scan of g_cnt -> g_start, zero cursors,
// dis = rsqrt(deg+1) (self loop), re-zero g_deg (invariant restore).
__global__ void k_scan_dis(int N, int E) {
    __shared__ int sh[1024];
    const int tid = threadIdx.x;
    const int per = (N + 1023) >> 10;
    const int base = tid * per;
    int s = 0;
    for (int i = 0; i < per; i++) {
        int idx = base + i;
        if (idx < N) s += g_cnt[idx];
    }
    sh[tid] = s;
    __syncthreads();
    for (int off = 1; off < 1024; off <<= 1) {
        int t = (tid >= off) ? sh[tid - off] : 0;
        __syncthreads();
        sh[tid] += t;
        __syncthreads();
    }
    int run = sh[tid] - s;
    for (int i = 0; i < per; i++) {
        int idx = base + i;
        if (idx < N) {
            int c = g_cnt[idx];
            g_start[idx] = run;
            run += c;
            g_cnt[idx] = 0;
            g_dis[idx] = rsqrtf((float)(g_deg[idx] + 1));
            g_deg[idx] = 0;   // restore invariant
        }
    }
    if (tid == 0) g_start[N] = E;
}

// Scatter edges into dst-sorted adjacency with per-edge weight dis[src].
__global__ void k_scatter(const void* p, int E) {
    __shared__ int s_flag;
    int is64 = detect_is64((const unsigned*)p, &s_flag);
    int e = blockIdx.x * blockDim.x + threadIdx.x;
    if (e >= E) return;
    int r, c;
    if (is64) {
        const long long* q = (const long long*)p;
        r = (int)q[e];
        c = (int)q[(long long)E + e];
    } else {
        const int* q = (const int*)p;
        r = q[e];
        c = q[E + e];
    }
    int pos = g_start[c] + atomicAdd(&g_cnt[c], 1);
    g_adj[pos] = make_int2(r, __float_as_int(g_dis[r]));
}

// ---------------------------------------------------------------------------
// Aggregation: one warp per dst node, fp32 float4 gather. 4 edges (loads) in
// flight for MLP; 2 accumulators to keep register count low -> higher occ.
// dst = dis[n]*(sum_e dis[src]*x[src]) + dis[n]^2 * x[n]
// ---------------------------------------------------------------------------
__global__ void __launch_bounds__(256)
k_agg(const float4* __restrict__ src, float4* __restrict__ dst, int N) {
    int w = (blockIdx.x * blockDim.x + threadIdx.x) >> 5;
    if (w >= N) return;
    const int lane = threadIdx.x & 31;
    int i = g_start[w];
    const int end = g_start[w + 1];

    float4 a0 = make_float4(0.f, 0.f, 0.f, 0.f);
    float4 a1 = make_float4(0.f, 0.f, 0.f, 0.f);

    for (; i + 4 <= end; i += 4) {
        int2 e0 = __ldg(&g_adj[i]);
        int2 e1 = __ldg(&g_adj[i + 1]);
        int2 e2 = __ldg(&g_adj[i + 2]);
        int2 e3 = __ldg(&g_adj[i + 3]);
        float4 v0 = __ldg(&src[(long)e0.x * DV + lane]);
        float4 v1 = __ldg(&src[(long)e1.x * DV + lane]);
        float4 v2 = __ldg(&src[(long)e2.x * DV + lane]);
        float4 v3 = __ldg(&src[(long)e3.x * DV + lane]);
        float w0 = __int_as_float(e0.y);
        float w1 = __int_as_float(e1.y);
        float w2 = __int_as_float(e2.y);
        float w3 = __int_as_float(e3.y);
        a0.x += w0 * v0.x; a0.y += w0 * v0.y; a0.z += w0 * v0.z; a0.w += w0 * v0.w;
        a1.x += w1 * v1.x; a1.y += w1 * v1.y; a1.z += w1 * v1.z; a1.w += w1 * v1.w;
        a0.x += w2 * v2.x; a0.y += w2 * v2.y; a0.z += w2 * v2.z; a0.w += w2 * v2.w;
        a1.x += w3 * v3.x; a1.y += w3 * v3.y; a1.z += w3 * v3.z; a1.w += w3 * v3.w;
    }
    for (; i < end; i++) {
        int2 e0 = __ldg(&g_adj[i]);
        float4 v0 = __ldg(&src[(long)e0.x * DV + lane]);
        float w0 = __int_as_float(e0.y);
        a0.x += w0 * v0.x; a0.y += w0 * v0.y; a0.z += w0 * v0.z; a0.w += w0 * v0.w;
    }

    float di = g_dis[w];
    float sw = di * di;
    float4 sv = __ldg(&src[(long)w * DV + lane]);
    float4 o;
    o.x = di * (a0.x + a1.x) + sw * sv.x;
    o.y = di * (a0.y + a1.y) + sw * sv.y;
    o.z = di * (a0.z + a1.z) + sw * sv.z;
    o.w = di * (a0.w + a1.w) + sw * sv.w;
    dst[(long)w * DV + lane] = o;
}

// ---------------------------------------------------------------------------
// GEMM (round-2 proven version): C = A @ W + bias, optional ReLU.
// BM=128, BN=128, BK=32, 256 threads, 8x8 register tile, smem staging.
// CLEAN re-zeroes g_cnt (invariant restore).
// ---------------------------------------------------------------------------
template <bool RELU, bool CLEAN>
__global__ void k_gemm(const float* __restrict__ A, const float* __restrict__ W,
                       const float* __restrict__ bias, float* __restrict__ C, int N) {
    __shared__ float As[32][129];   // [k][m]
    __shared__ float Ws[32][128];   // [k][n]

    const int tid = threadIdx.x;
    if (CLEAN) {
        int idx = blockIdx.x * blockDim.x + tid;
        if (idx < MAXN) g_cnt[idx] = 0;
    }
    const int tm = tid >> 4;    // 0..15 -> 8 rows each
    const int tn = tid & 15;    // 0..15 -> 8 cols each
    const int row0 = blockIdx.x * 128;

    float acc[8][8];
    #pragma unroll
    for (int i = 0; i < 8; i++)
        #pragma unroll
        for (int j = 0; j < 8; j++) acc[i][j] = 0.f;

    for (int kk = 0; kk < D; kk += 32) {
        #pragma unroll
        for (int it = 0; it < 4; it++) {
            int idx = tid + it * 256;
            int m  = idx >> 3;       // row in tile (0..127)
            int k4 = idx & 7;        // float4 index along k (0..7)
            float4 v = make_float4(0.f, 0.f, 0.f, 0.f);
            int gr = row0 + m;
            if (gr < N) v = *(const float4*)(A + (long)gr * D + kk + k4 * 4);
            As[k4 * 4 + 0][m] = v.x;
            As[k4 * 4 + 1][m] = v.y;
            As[k4 * 4 + 2][m] = v.z;
            As[k4 * 4 + 3][m] = v.w;
        }
        #pragma unroll
        for (int it = 0; it < 4; it++) {
            int idx = tid + it * 256;
            int k  = idx >> 5;
            int n4 = idx & 31;
            *(float4*)&Ws[k][n4 * 4] = *(const float4*)(W + (kk + k) * D + n4 * 4);
        }
        __syncthreads();

        #pragma unroll 8
        for (int k = 0; k < 32; k++) {
            float a[8], b[8];
            #pragma unroll
            for (int j = 0; j < 8; j++) a[j] = As[k][tm * 8 + j];
            float4 b0 = *(const float4*)&Ws[k][tn * 8];
            float4 b1 = *(const float4*)&Ws[k][tn * 8 + 4];
            b[0] = b0.x; b[1] = b0.y; b[2] = b0.z; b[3] = b0.w;
            b[4] = b1.x; b[5] = b1.y; b[6] = b1.z; b[7] = b1.w;
            #pragma unroll
            for (int i = 0; i < 8; i++)
                #pragma unroll
                for (int j = 0; j < 8; j++)
                    acc[i][j] += a[i] * b[j];
        }
        __syncthreads();
    }

    float4 bv0 = *(const float4*)(bias + tn * 8);
    float4 bv1 = *(const float4*)(bias + tn * 8 + 4);
    #pragma unroll
    for (int i = 0; i < 8; i++) {
        int gr = row0 + tm * 8 + i;
        if (gr >= N) continue;
        float o[8];
        o[0] = acc[i][0] + bv0.x; o[1] = acc[i][1] + bv0.y;
        o[2] = acc[i][2] + bv0.z; o[3] = acc[i][3] + bv0.w;
        o[4] = acc[i][4] + bv1.x; o[5] = acc[i][5] + bv1.y;
        o[6] = acc[i][6] + bv1.z; o[7] = acc[i][7] + bv1.w;
        if (RELU) {
            #pragma unroll
            for (int j = 0; j < 8; j++) o[j] = fmaxf(o[j], 0.f);
        }
        *(float4*)(C + (long)gr * D + tn * 8)     = make_float4(o[0], o[1], o[2], o[3]);
        *(float4*)(C + (long)gr * D + tn * 8 + 4) = make_float4(o[4], o[5], o[6], o[7]);
    }
}

extern "C" void kernel_launch(void* const* d_in, const int* in_sizes, int n_in,
                              void* d_out, int out_size) {
    const float* x  = (const float*)d_in[0];
    const void*  ei = d_in[1];
    const float* W1 = (const float*)d_in[2];
    const float* b1 = (const float*)d_in[3];
    const float* W2 = (const float*)d_in[4];
    const float* b2 = (const float*)d_in[5];
    float* out = (float*)d_out;

    const int N = in_sizes[0] / D;
    const int E = in_sizes[1] / 2;

    float* a_ptr = nullptr;
    float* h_ptr = nullptr;
    cudaGetSymbolAddress((void**)&a_ptr, g_a);
    cudaGetSymbolAddress((void**)&h_ptr, g_h);

    const int T = 256;
    const int eGrid = (E + T - 1) / T;
    const int aggGrid  = (N * 32 + T - 1) / T;
    const int gemmGrid = (N + 127) / 128;

    // ---- prep (3 launches; deg/cnt arrive zeroed by invariant) ----
    k_prep<<<eGrid, T>>>(ei, E);
    k_scan_dis<<<1, 1024>>>(N, E);
    k_scatter<<<eGrid, T>>>(ei, E);

    // ---- layer 1 ----
    k_agg<<<aggGrid, T>>>((const float4*)x, (float4*)a_ptr, N);
    k_gemm<true, false><<<gemmGrid, T>>>(a_ptr, W1, b1, h_ptr, N);

    // ---- layer 2 (final gemm restores g_cnt = 0) ----
    k_agg<<<aggGrid, T>>>((const float4*)h_ptr, (float4*)a_ptr, N);
    k_gemm<false, true><<<gemmGrid, T>>>(a_ptr, W2, b2, out, N);
}

// round 7
// speedup vs baseline: 1.2000x; 1.1414x over previous
#include <cuda_runtime.h>
#include <stdint.h>

#define D 128
#define DV 32              // float4 chunks per row
#define MAXN 50048
#define MAXE 1600000

// Zero-initialized at module load. Invariant: g_deg and g_cnt are all-zero at
// entry to kernel_launch, and every call restores that before it returns
// (k_scan_dis zeroes deg; the final k_agg zeroes cnt).
__device__ int      g_deg[MAXN];
__device__ int      g_cnt[MAXN];
__device__ int2     g_adj[MAXE];        // dst-sorted: {src, bits(dis[src])}
__device__ int      g_start[MAXN + 1];  // CSR offsets by dst
__device__ float    g_dis[MAXN];
__device__ float    g_t[MAXN * D];      // GEMM output (pre-aggregation)
__device__ float    g_h[MAXN * D];      // hidden after layer 1
__device__ unsigned g_w1t[D * D];       // W1 as tf32 bit patterns
__device__ unsigned g_w2t[D * D];       // W2 as tf32 bit patterns

__device__ __forceinline__ unsigned f2tf32(float f) {
    unsigned u;
    asm("cvt.rna.tf32.f32 %0, %1;" : "=r"(u) : "f"(f));
    return u;
}

// ---------------------------------------------------------------------------
// Convert both weight matrices to tf32 bit patterns (one launch).
// ---------------------------------------------------------------------------
__global__ void k_cvtW(const float* __restrict__ W1, const float* __restrict__ W2) {
    int i = blockIdx.x * blockDim.x + threadIdx.x;
    if (i < D * D)          g_w1t[i]         = f2tf32(W1[i]);
    else if (i < 2 * D * D) g_w2t[i - D * D] = f2tf32(W2[i - D * D]);
}

// ---------------------------------------------------------------------------
// Per-block dtype detect: int64 little-endian values < 2^32 -> odd 32-bit
// words all zero over 128 samples.
// ---------------------------------------------------------------------------
__device__ __forceinline__ int detect_is64(const unsigned* p, int* s_flag) {
    if (threadIdx.x == 0) *s_flag = 0;
    __syncthreads();
    if (threadIdx.x < 64) {
        unsigned nz = p[2 * threadIdx.x + 1] | p[2 * threadIdx.x + 129];
        if (nz) atomicOr(s_flag, 1);
    }
    __syncthreads();
    return *s_flag ? 0 : 1;
}

__global__ void k_prep(const void* p, int E) {
    __shared__ int s_flag;
    int is64 = detect_is64((const unsigned*)p, &s_flag);
    int e = blockIdx.x * blockDim.x + threadIdx.x;
    if (e >= E) return;
    int r, c;
    if (is64) {
        const long long* q = (const long long*)p;
        r = (int)q[e];
        c = (int)q[(long long)E + e];
    } else {
        const int* q = (const int*)p;
        r = q[e];
        c = q[E + e];
    }
    atomicAdd(&g_deg[r], 1);
    atomicAdd(&g_cnt[c], 1);
}

// Single block: exclusive scan g_cnt -> g_start, zero cursors,
// dis = rsqrt(deg+1) (self loop), re-zero g_deg (invariant restore).
__global__ void k_scan_dis(int N, int E) {
    __shared__ int sh[1024];
    const int tid = threadIdx.x;
    const int per = (N + 1023) >> 10;
    const int base = tid * per;
    int s = 0;
    for (int i = 0; i < per; i++) {
        int idx = base + i;
        if (idx < N) s += g_cnt[idx];
    }
    sh[tid] = s;
    __syncthreads();
    for (int off = 1; off < 1024; off <<= 1) {
        int t = (tid >= off) ? sh[tid - off] : 0;
        __syncthreads();
        sh[tid] += t;
        __syncthreads();
    }
    int run = sh[tid] - s;
    for (int i = 0; i < per; i++) {
        int idx = base + i;
        if (idx < N) {
            int c = g_cnt[idx];
            g_start[idx] = run;
            run += c;
            g_cnt[idx] = 0;
            g_dis[idx] = rsqrtf((float)(g_deg[idx] + 1));
            g_deg[idx] = 0;
        }
    }
    if (tid == 0) g_start[N] = E;
}

__global__ void k_scatter(const void* p, int E) {
    __shared__ int s_flag;
    int is64 = detect_is64((const unsigned*)p, &s_flag);
    int e = blockIdx.x * blockDim.x + threadIdx.x;
    if (e >= E) return;
    int r, c;
    if (is64) {
        const long long* q = (const long long*)p;
        r = (int)q[e];
        c = (int)q[(long long)E + e];
    } else {
        const int* q = (const int*)p;
        r = q[e];
        c = q[E + e];
    }
    int pos = g_start[c] + atomicAdd(&g_cnt[c], 1);
    g_adj[pos] = make_int2(r, __float_as_int(g_dis[r]));
}

// ---------------------------------------------------------------------------
// GEMM (tf32 tensor cores): C[N,128] = A[N,128] @ W[128,128]  (no bias).
// 256 threads = 8 warps (2 m x 4 n); per warp 4x4 m16n8k8 tiles (64x32).
// A staged per-32k-slab in smem as tf32 bits, [m][36] padding ->
// fragment read bank = (4g+t)%32, conflict-free. W frags straight from L1.
// ---------------------------------------------------------------------------
__global__ void __launch_bounds__(256)
k_gemm_tf32(const float* __restrict__ A, const unsigned* __restrict__ Wt,
            float* __restrict__ C, int N) {
    __shared__ unsigned As[128][36];

    const int tid  = threadIdx.x;
    const int wid  = tid >> 5;
    const int lane = tid & 31;
    const int g    = lane >> 2;     // groupID
    const int t    = lane & 3;      // threadID_in_group
    const int wm   = wid >> 2;      // 0..1  -> 64-row half
    const int wn   = wid & 3;       // 0..3  -> 32-col quarter
    const int row0 = blockIdx.x * 128;

    float acc[4][4][4];
    #pragma unroll
    for (int mt = 0; mt < 4; mt++)
        #pragma unroll
        for (int nt = 0; nt < 4; nt++)
            #pragma unroll
            for (int c = 0; c < 4; c++) acc[mt][nt][c] = 0.f;

    for (int kk = 0; kk < D; kk += 32) {
        // Stage A slab: 128 rows x 32 k. Coalesced float4 loads, cvt to tf32.
        #pragma unroll
        for (int it = 0; it < 4; it++) {
            int idx = tid + it * 256;
            int m  = idx >> 3;        // 0..127
            int k4 = idx & 7;         // 0..7
            float4 v = make_float4(0.f, 0.f, 0.f, 0.f);
            int gr = row0 + m;
            if (gr < N) v = *(const float4*)(A + (long)gr * D + kk + k4 * 4);
            As[m][k4 * 4 + 0] = f2tf32(v.x);
            As[m][k4 * 4 + 1] = f2tf32(v.y);
            As[m][k4 * 4 + 2] = f2tf32(v.z);
            As[m][k4 * 4 + 3] = f2tf32(v.w);
        }
        __syncthreads();

        #pragma unroll
        for (int ks = 0; ks < 4; ks++) {
            const int kb = kk + ks * 8;
            // W fragments (b0 = W[kb+t][n], b1 = W[kb+t+4][n]); L1-resident.
            unsigned bf[4][2];
            #pragma unroll
            for (int nt = 0; nt < 4; nt++) {
                int n = wn * 32 + nt * 8 + g;
                bf[nt][0] = __ldg(&Wt[(kb + t) * D + n]);
                bf[nt][1] = __ldg(&Wt[(kb + t + 4) * D + n]);
            }
            #pragma unroll
            for (int mt = 0; mt < 4; mt++) {
                int mb = wm * 64 + mt * 16;
                unsigned a0 = As[mb + g    ][ks * 8 + t    ];
                unsigned a1 = As[mb + g + 8][ks * 8 + t    ];
                unsigned a2 = As[mb + g    ][ks * 8 + t + 4];
                unsigned a3 = As[mb + g + 8][ks * 8 + t + 4];
                #pragma unroll
                for (int nt = 0; nt < 4; nt++) {
                    asm volatile(
                        "mma.sync.aligned.m16n8k8.row.col.f32.tf32.tf32.f32 "
                        "{%0,%1,%2,%3}, {%4,%5,%6,%7}, {%8,%9}, {%0,%1,%2,%3};"
                        : "+f"(acc[mt][nt][0]), "+f"(acc[mt][nt][1]),
                          "+f"(acc[mt][nt][2]), "+f"(acc[mt][nt][3])
                        : "r"(a0), "r"(a1), "r"(a2), "r"(a3),
                          "r"(bf[nt][0]), "r"(bf[nt][1]));
                }
            }
        }
        __syncthreads();
    }

    // Epilogue: c0=[g][2t], c1=[g][2t+1], c2=[g+8][2t], c3=[g+8][2t+1]
    #pragma unroll
    for (int mt = 0; mt < 4; mt++) {
        int r0 = row0 + wm * 64 + mt * 16 + g;
        int r1 = r0 + 8;
        #pragma unroll
        for (int nt = 0; nt < 4; nt++) {
            int n = wn * 32 + nt * 8 + 2 * t;
            if (r0 < N)
                *(float2*)(C + (long)r0 * D + n) = make_float2(acc[mt][nt][0], acc[mt][nt][1]);
            if (r1 < N)
                *(float2*)(C + (long)r1 * D + n) = make_float2(acc[mt][nt][2], acc[mt][nt][3]);
        }
    }
}

// ---------------------------------------------------------------------------
// Aggregation (+ bias, optional ReLU): one warp per dst node, fp32 gather,
// 4 loads in flight, 2 accumulators (regs=32 -> occ 82%, measured 52us).
// out = dis[n]*(sum_e dis[src]*t[src]) + dis[n]^2 * t[n] + bias
// ---------------------------------------------------------------------------
template <bool RELU, bool CLEAN>
__global__ void __launch_bounds__(256)
k_agg(const float4* __restrict__ src, const float4* __restrict__ bias4,
      float4* __restrict__ dst, int N) {
    if (CLEAN) {
        int idx = blockIdx.x * blockDim.x + threadIdx.x;
        if (idx < MAXN) g_cnt[idx] = 0;   // restore invariant
    }
    int w = (blockIdx.x * blockDim.x + threadIdx.x) >> 5;
    if (w >= N) return;
    const int lane = threadIdx.x & 31;
    int i = g_start[w];
    const int end = g_start[w + 1];

    float4 a0 = make_float4(0.f, 0.f, 0.f, 0.f);
    float4 a1 = make_float4(0.f, 0.f, 0.f, 0.f);

    for (; i + 4 <= end; i += 4) {
        int2 e0 = __ldg(&g_adj[i]);
        int2 e1 = __ldg(&g_adj[i + 1]);
        int2 e2 = __ldg(&g_adj[i + 2]);
        int2 e3 = __ldg(&g_adj[i + 3]);
        float4 v0 = __ldg(&src[(long)e0.x * DV + lane]);
        float4 v1 = __ldg(&src[(long)e1.x * DV + lane]);
        float4 v2 = __ldg(&src[(long)e2.x * DV + lane]);
        float4 v3 = __ldg(&src[(long)e3.x * DV + lane]);
        float w0 = __int_as_float(e0.y);
        float w1 = __int_as_float(e1.y);
        float w2 = __int_as_float(e2.y);
        float w3 = __int_as_float(e3.y);
        a0.x += w0 * v0.x; a0.y += w0 * v0.y; a0.z += w0 * v0.z; a0.w += w0 * v0.w;
        a1.x += w1 * v1.x; a1.y += w1 * v1.y; a1.z += w1 * v1.z; a1.w += w1 * v1.w;
        a0.x += w2 * v2.x; a0.y += w2 * v2.y; a0.z += w2 * v2.z; a0.w += w2 * v2.w;
        a1.x += w3 * v3.x; a1.y += w3 * v3.y; a1.z += w3 * v3.z; a1.w += w3 * v3.w;
    }
    for (; i < end; i++) {
        int2 e0 = __ldg(&g_adj[i]);
        float4 v0 = __ldg(&src[(long)e0.x * DV + lane]);
        float w0 = __int_as_float(e0.y);
        a0.x += w0 * v0.x; a0.y += w0 * v0.y; a0.z += w0 * v0.z; a0.w += w0 * v0.w;
    }

    float di = g_dis[w];
    float sw = di * di;
    float4 sv = __ldg(&src[(long)w * DV + lane]);
    float4 bv = __ldg(&bias4[lane]);
    float4 o;
    o.x = di * (a0.x + a1.x) + sw * sv.x + bv.x;
    o.y = di * (a0.y + a1.y) + sw * sv.y + bv.y;
    o.z = di * (a0.z + a1.z) + sw * sv.z + bv.z;
    o.w = di * (a0.w + a1.w) + sw * sv.w + bv.w;
    if (RELU) {
        o.x = fmaxf(o.x, 0.f); o.y = fmaxf(o.y, 0.f);
        o.z = fmaxf(o.z, 0.f); o.w = fmaxf(o.w, 0.f);
    }
    dst[(long)w * DV + lane] = o;
}

extern "C" void kernel_launch(void* const* d_in, const int* in_sizes, int n_in,
                              void* d_out, int out_size) {
    const float* x  = (const float*)d_in[0];
    const void*  ei = d_in[1];
    const float* W1 = (const float*)d_in[2];
    const float* b1 = (const float*)d_in[3];
    const float* W2 = (const float*)d_in[4];
    const float* b2 = (const float*)d_in[5];
    float* out = (float*)d_out;

    const int N = in_sizes[0] / D;
    const int E = in_sizes[1] / 2;

    float*    t_ptr = nullptr;
    float*    h_ptr = nullptr;
    unsigned* w1t   = nullptr;
    unsigned* w2t   = nullptr;
    cudaGetSymbolAddress((void**)&t_ptr, g_t);
    cudaGetSymbolAddress((void**)&h_ptr, g_h);
    cudaGetSymbolAddress((void**)&w1t,   g_w1t);
    cudaGetSymbolAddress((void**)&w2t,   g_w2t);

    const int T = 256;
    const int eGrid    = (E + T - 1) / T;
    const int aggGrid  = (N * 32 + T - 1) / T;
    const int gemmGrid = (N + 127) / 128;

    // Uses GEMM/Agg commutativity: Agg(x)@W = Agg(x@W); bias+ReLU fold
    // into the agg epilogue. GEMM1 is launch #4 (ncu sample slot).
    k_cvtW<<<(2 * D * D + T - 1) / T, T>>>(W1, W2);                       // 1
    k_prep<<<eGrid, T>>>(ei, E);                                          // 2
    k_scan_dis<<<1, 1024>>>(N, E);                                        // 3
    k_gemm_tf32<<<gemmGrid, T>>>(x, w1t, t_ptr, N);                       // 4
    k_scatter<<<eGrid, T>>>(ei, E);                                       // 5
    k_agg<true, false><<<aggGrid, T>>>((const float4*)t_ptr,              // 6
                                       (const float4*)b1, (float4*)h_ptr, N);
    k_gemm_tf32<<<gemmGrid, T>>>(h_ptr, w2t, t_ptr, N);                   // 7
    k_agg<false, true><<<aggGrid, T>>>((const float4*)t_ptr,              // 8
                                       (const float4*)b2, (float4*)out, N);
}

// round 8
// speedup vs baseline: 1.2136x; 1.0114x over previous
#include <cuda_runtime.h>
#include <stdint.h>

#define D 128
#define DV 32              // float4 chunks per row
#define MAXN 50048
#define MAXE 1600000

// Zero-initialized at module load. Invariant: g_deg and g_cnt are all-zero at
// entry to kernel_launch, and every call restores that before it returns
// (k_scan_dis zeroes deg; the final k_agg zeroes cnt).
__device__ int      g_deg[MAXN];
__device__ int      g_cnt[MAXN];
__device__ int2     g_adj[MAXE];        // dst-sorted: {src, bits(dis[src])}
__device__ int      g_start[MAXN + 1];  // CSR offsets by dst
__device__ float    g_dis[MAXN];
__device__ float    g_t[MAXN * D];      // GEMM output (pre-aggregation)
__device__ float    g_h[MAXN * D];      // hidden after layer 1
__device__ unsigned g_w1t[D * D];       // W1 as tf32 bit patterns
__device__ unsigned g_w2t[D * D];       // W2 as tf32 bit patterns

__device__ __forceinline__ unsigned f2tf32(float f) {
    unsigned u;
    asm("cvt.rna.tf32.f32 %0, %1;" : "=r"(u) : "f"(f));
    return u;
}

// ---------------------------------------------------------------------------
// Per-block dtype detect: int64 little-endian values < 2^32 -> odd 32-bit
// words all zero over 128 samples.
// ---------------------------------------------------------------------------
__device__ __forceinline__ int detect_is64(const unsigned* p, int* s_flag) {
    if (threadIdx.x == 0) *s_flag = 0;
    __syncthreads();
    if (threadIdx.x < 64) {
        unsigned nz = p[2 * threadIdx.x + 1] | p[2 * threadIdx.x + 129];
        if (nz) atomicOr(s_flag, 1);
    }
    __syncthreads();
    return *s_flag ? 0 : 1;
}

// Parse edges (either dtype) and count degrees. First 128 blocks also convert
// the weight matrices to tf32 bit patterns (fused k_cvtW).
__global__ void k_prep(const void* p, int E,
                       const float* __restrict__ W1, const float* __restrict__ W2) {
    __shared__ int s_flag;
    int is64 = detect_is64((const unsigned*)p, &s_flag);
    int gt = blockIdx.x * blockDim.x + threadIdx.x;
    if (gt < D * D)          g_w1t[gt]         = f2tf32(W1[gt]);
    else if (gt < 2 * D * D) g_w2t[gt - D * D] = f2tf32(W2[gt - D * D]);
    int e = gt;
    if (e >= E) return;
    int r, c;
    if (is64) {
        const long long* q = (const long long*)p;
        r = (int)q[e];
        c = (int)q[(long long)E + e];
    } else {
        const int* q = (const int*)p;
        r = q[e];
        c = q[E + e];
    }
    atomicAdd(&g_deg[r], 1);
    atomicAdd(&g_cnt[c], 1);
}

// Single block: exclusive scan g_cnt -> g_start, zero cursors,
// dis = rsqrt(deg+1) (self loop), re-zero g_deg (invariant restore).
__global__ void k_scan_dis(int N, int E) {
    __shared__ int sh[1024];
    const int tid = threadIdx.x;
    const int per = (N + 1023) >> 10;
    const int base = tid * per;
    int s = 0;
    for (int i = 0; i < per; i++) {
        int idx = base + i;
        if (idx < N) s += g_cnt[idx];
    }
    sh[tid] = s;
    __syncthreads();
    for (int off = 1; off < 1024; off <<= 1) {
        int t = (tid >= off) ? sh[tid - off] : 0;
        __syncthreads();
        sh[tid] += t;
        __syncthreads();
    }
    int run = sh[tid] - s;
    for (int i = 0; i < per; i++) {
        int idx = base + i;
        if (idx < N) {
            int c = g_cnt[idx];
            g_start[idx] = run;
            run += c;
            g_cnt[idx] = 0;
            g_dis[idx] = rsqrtf((float)(g_deg[idx] + 1));
            g_deg[idx] = 0;
        }
    }
    if (tid == 0) g_start[N] = E;
}

__global__ void k_scatter(const void* p, int E) {
    __shared__ int s_flag;
    int is64 = detect_is64((const unsigned*)p, &s_flag);
    int e = blockIdx.x * blockDim.x + threadIdx.x;
    if (e >= E) return;
    int r, c;
    if (is64) {
        const long long* q = (const long long*)p;
        r = (int)q[e];
        c = (int)q[(long long)E + e];
    } else {
        const int* q = (const int*)p;
        r = q[e];
        c = q[E + e];
    }
    int pos = g_start[c] + atomicAdd(&g_cnt[c], 1);
    g_adj[pos] = make_int2(r, __float_as_int(g_dis[r]));
}

// ---------------------------------------------------------------------------
// GEMM (tf32 tensor cores): C[N,128] = A[N,128] @ W[128,128]  (no bias).
// BM=64, BN=128: 256 threads = 8 warps (2 m x 4 n); warp tile 32x32
// (2x4 m16n8k8), acc = 32 regs/thread -> 3 blocks/SM.
// A staged per-32k-slab in smem as tf32 bits, [m][36] pad = conflict-free.
// W fragments via __ldg (L1-resident, 64KB).
// ---------------------------------------------------------------------------
__global__ void __launch_bounds__(256, 3)
k_gemm_tf32(const float* __restrict__ A, const unsigned* __restrict__ Wt,
            float* __restrict__ C, int N) {
    __shared__ unsigned As[64][36];

    const int tid  = threadIdx.x;
    const int wid  = tid >> 5;
    const int lane = tid & 31;
    const int g    = lane >> 2;     // groupID
    const int t    = lane & 3;      // threadID_in_group
    const int wm   = wid >> 2;      // 0..1  -> 32-row half
    const int wn   = wid & 3;       // 0..3  -> 32-col quarter
    const int row0 = blockIdx.x * 64;

    float acc[2][4][4];
    #pragma unroll
    for (int mt = 0; mt < 2; mt++)
        #pragma unroll
        for (int nt = 0; nt < 4; nt++)
            #pragma unroll
            for (int c = 0; c < 4; c++) acc[mt][nt][c] = 0.f;

    for (int kk = 0; kk < D; kk += 32) {
        // Stage A slab: 64 rows x 32 k. Coalesced float4 loads, cvt to tf32.
        #pragma unroll
        for (int it = 0; it < 2; it++) {
            int idx = tid + it * 256;
            int m  = idx >> 3;        // 0..63
            int k4 = idx & 7;         // 0..7
            float4 v = make_float4(0.f, 0.f, 0.f, 0.f);
            int gr = row0 + m;
            if (gr < N) v = *(const float4*)(A + (long)gr * D + kk + k4 * 4);
            As[m][k4 * 4 + 0] = f2tf32(v.x);
            As[m][k4 * 4 + 1] = f2tf32(v.y);
            As[m][k4 * 4 + 2] = f2tf32(v.z);
            As[m][k4 * 4 + 3] = f2tf32(v.w);
        }
        __syncthreads();

        #pragma unroll
        for (int ks = 0; ks < 4; ks++) {
            const int kb = kk + ks * 8;
            unsigned bf[4][2];
            #pragma unroll
            for (int nt = 0; nt < 4; nt++) {
                int n = wn * 32 + nt * 8 + g;
                bf[nt][0] = __ldg(&Wt[(kb + t) * D + n]);
                bf[nt][1] = __ldg(&Wt[(kb + t + 4) * D + n]);
            }
            #pragma unroll
            for (int mt = 0; mt < 2; mt++) {
                int mb = wm * 32 + mt * 16;
                unsigned a0 = As[mb + g    ][ks * 8 + t    ];
                unsigned a1 = As[mb + g + 8][ks * 8 + t    ];
                unsigned a2 = As[mb + g    ][ks * 8 + t + 4];
                unsigned a3 = As[mb + g + 8][ks * 8 + t + 4];
                #pragma unroll
                for (int nt = 0; nt < 4; nt++) {
                    asm volatile(
                        "mma.sync.aligned.m16n8k8.row.col.f32.tf32.tf32.f32 "
                        "{%0,%1,%2,%3}, {%4,%5,%6,%7}, {%8,%9}, {%0,%1,%2,%3};"
                        : "+f"(acc[mt][nt][0]), "+f"(acc[mt][nt][1]),
                          "+f"(acc[mt][nt][2]), "+f"(acc[mt][nt][3])
                        : "r"(a0), "r"(a1), "r"(a2), "r"(a3),
                          "r"(bf[nt][0]), "r"(bf[nt][1]));
                }
            }
        }
        __syncthreads();
    }

    // Epilogue: c0=[g][2t], c1=[g][2t+1], c2=[g+8][2t], c3=[g+8][2t+1]
    #pragma unroll
    for (int mt = 0; mt < 2; mt++) {
        int r0 = row0 + wm * 32 + mt * 16 + g;
        int r1 = r0 + 8;
        #pragma unroll
        for (int nt = 0; nt < 4; nt++) {
            int n = wn * 32 + nt * 8 + 2 * t;
            if (r0 < N)
                *(float2*)(C + (long)r0 * D + n) = make_float2(acc[mt][nt][0], acc[mt][nt][1]);
            if (r1 < N)
                *(float2*)(C + (long)r1 * D + n) = make_float2(acc[mt][nt][2], acc[mt][nt][3]);
        }
    }
}

// ---------------------------------------------------------------------------
// Aggregation (+ bias, optional ReLU): one warp per dst node, fp32 gather,
// 4 loads in flight, 2 accumulators (regs=32, occ 82%, measured 52us).
// out = dis[n]*(sum_e dis[src]*t[src]) + dis[n]^2 * t[n] + bias
// ---------------------------------------------------------------------------
template <bool RELU, bool CLEAN>
__global__ void __launch_bounds__(256)
k_agg(const float4* __restrict__ src, const float4* __restrict__ bias4,
      float4* __restrict__ dst, int N) {
    if (CLEAN) {
        int idx = blockIdx.x * blockDim.x + threadIdx.x;
        if (idx < MAXN) g_cnt[idx] = 0;   // restore invariant
    }
    int w = (blockIdx.x * blockDim.x + threadIdx.x) >> 5;
    if (w >= N) return;
    const int lane = threadIdx.x & 31;
    int i = g_start[w];
    const int end = g_start[w + 1];

    float4 a0 = make_float4(0.f, 0.f, 0.f, 0.f);
    float4 a1 = make_float4(0.f, 0.f, 0.f, 0.f);

    for (; i + 4 <= end; i += 4) {
        int2 e0 = __ldg(&g_adj[i]);
        int2 e1 = __ldg(&g_adj[i + 1]);
        int2 e2 = __ldg(&g_adj[i + 2]);
        int2 e3 = __ldg(&g_adj[i + 3]);
        float4 v0 = __ldg(&src[(long)e0.x * DV + lane]);
        float4 v1 = __ldg(&src[(long)e1.x * DV + lane]);
        float4 v2 = __ldg(&src[(long)e2.x * DV + lane]);
        float4 v3 = __ldg(&src[(long)e3.x * DV + lane]);
        float w0 = __int_as_float(e0.y);
        float w1 = __int_as_float(e1.y);
        float w2 = __int_as_float(e2.y);
        float w3 = __int_as_float(e3.y);
        a0.x += w0 * v0.x; a0.y += w0 * v0.y; a0.z += w0 * v0.z; a0.w += w0 * v0.w;
        a1.x += w1 * v1.x; a1.y += w1 * v1.y; a1.z += w1 * v1.z; a1.w += w1 * v1.w;
        a0.x += w2 * v2.x; a0.y += w2 * v2.y; a0.z += w2 * v2.z; a0.w += w2 * v2.w;
        a1.x += w3 * v3.x; a1.y += w3 * v3.y; a1.z += w3 * v3.z; a1.w += w3 * v3.w;
    }
    for (; i < end; i++) {
        int2 e0 = __ldg(&g_adj[i]);
        float4 v0 = __ldg(&src[(long)e0.x * DV + lane]);
        float w0 = __int_as_float(e0.y);
        a0.x += w0 * v0.x; a0.y += w0 * v0.y; a0.z += w0 * v0.z; a0.w += w0 * v0.w;
    }

    float di = g_dis[w];
    float sw = di * di;
    float4 sv = __ldg(&src[(long)w * DV + lane]);
    float4 bv = __ldg(&bias4[lane]);
    float4 o;
    o.x = di * (a0.x + a1.x) + sw * sv.x + bv.x;
    o.y = di * (a0.y + a1.y) + sw * sv.y + bv.y;
    o.z = di * (a0.z + a1.z) + sw * sv.z + bv.z;
    o.w = di * (a0.w + a1.w) + sw * sv.w + bv.w;
    if (RELU) {
        o.x = fmaxf(o.x, 0.f); o.y = fmaxf(o.y, 0.f);
        o.z = fmaxf(o.z, 0.f); o.w = fmaxf(o.w, 0.f);
    }
    dst[(long)w * DV + lane] = o;
}

extern "C" void kernel_launch(void* const* d_in, const int* in_sizes, int n_in,
                              void* d_out, int out_size) {
    const float* x  = (const float*)d_in[0];
    const void*  ei = d_in[1];
    const float* W1 = (const float*)d_in[2];
    const float* b1 = (const float*)d_in[3];
    const float* W2 = (const float*)d_in[4];
    const float* b2 = (const float*)d_in[5];
    float* out = (float*)d_out;

    const int N = in_sizes[0] / D;
    const int E = in_sizes[1] / 2;

    float*    t_ptr = nullptr;
    float*    h_ptr = nullptr;
    unsigned* w1t   = nullptr;
    unsigned* w2t   = nullptr;
    cudaGetSymbolAddress((void**)&t_ptr, g_t);
    cudaGetSymbolAddress((void**)&h_ptr, g_h);
    cudaGetSymbolAddress((void**)&w1t,   g_w1t);
    cudaGetSymbolAddress((void**)&w2t,   g_w2t);

    const int T = 256;
    const int eGrid    = (E + T - 1) / T;
    const int aggGrid  = (N * 32 + T - 1) / T;
    const int gemmGrid = (N + 63) / 64;

    // Uses GEMM/Agg commutativity: Agg(x)@W = Agg(x@W); bias+ReLU fold into
    // the agg epilogue. GEMM1 is launch #4 (ncu sample slot).
    k_prep<<<eGrid, T>>>(ei, E, W1, W2);                                  // 1
    k_scan_dis<<<1, 1024>>>(N, E);                                        // 2
    k_scatter<<<eGrid, T>>>(ei, E);                                       // 3
    k_gemm_tf32<<<gemmGrid, T>>>(x, w1t, t_ptr, N);                       // 4
    k_agg<true, false><<<aggGrid, T>>>((const float4*)t_ptr,              // 5
                                       (const float4*)b1, (float4*)h_ptr, N);
    k_gemm_tf32<<<gemmGrid, T>>>(h_ptr, w2t, t_ptr, N);                   // 6
    k_agg<false, true><<<aggGrid, T>>>((const float4*)t_ptr,              // 7
                                       (const float4*)b2, (float4*)out, N);
}